// round 14
// baseline (speedup 1.0000x reference)
#include <cuda_runtime.h>
#include <cuda_fp16.h>
#include <cuda_pipeline.h>
#include <mma.h>

using namespace nvcuda;

#define B_   2
#define S_   2048
#define H_   16
#define DH_  64
#define D_   1024
#define M_   (B_ * S_)
#define N3_  (3 * D_)

// fp16 scratch (device globals; no allocs allowed)
__device__ __half g_xh[M_ * D_];
__device__ __half g_wih[N3_ * D_];
__device__ __half g_woh[D_ * D_];
__device__ __half g_qh[M_ * D_];
__device__ __half g_kh[M_ * D_];
__device__ __half g_vh[M_ * D_];
__device__ __half g_attnh[M_ * D_];

// ---------------- fused fp32 -> fp16 for x, W_in, W_out ----------------
#define NA2 (M_ * D_ / 2)
#define NB2 (N3_ * D_ / 2)
#define NC2 (D_ * D_ / 2)

__global__ void f2h3(const float* __restrict__ a, const float* __restrict__ b,
                     const float* __restrict__ c,
                     __half2* __restrict__ da, __half2* __restrict__ db,
                     __half2* __restrict__ dc) {
    int i = blockIdx.x * blockDim.x + threadIdx.x;
    if (i < NA2) {
        float2 v = reinterpret_cast<const float2*>(a)[i];
        da[i] = __floats2half2_rn(v.x, v.y);
    } else if (i < NA2 + NB2) {
        int j = i - NA2;
        float2 v = reinterpret_cast<const float2*>(b)[j];
        db[j] = __floats2half2_rn(v.x, v.y);
    } else {
        int j = i - NA2 - NB2;
        float2 v = reinterpret_cast<const float2*>(c)[j];
        dc[j] = __floats2half2_rn(v.x, v.y);
    }
}

// ---------------------------------------------------------------------------
// WMMA fp16 GEMM, block 128x64, warp tile 32x32 (4x2 warps, 256 thr),
// BK=32, 3-stage cp.async, 3 CTAs/SM target: C = A @ Wt^T + bias.
// mode 0: fp32 out to Cf. mode 1: scatter half to g_qh/g_kh/g_vh.
// A == nullptr means read g_attnh.
// ---------------------------------------------------------------------------
#define PADH 40
#define CPAD 20
#define GSTG 3
#define ATILEH (128 * PADH)          // A tile halves per stage
#define BTILEH (64 * PADH)           // B tile halves per stage
#define STGH (ATILEH + BTILEH)       // halves per stage
#define HG_SMEM ((GSTG * STGH) * 2 + 8 * 16 * CPAD * 4)

__global__ __launch_bounds__(256, 3) void hgemm(
    const __half* __restrict__ A, const __half* __restrict__ Wt,
    const float* __restrict__ bias, float* __restrict__ Cf,
    int N, int K, int mode)
{
    extern __shared__ char hsm[];
    __half* Sm = reinterpret_cast<__half*>(hsm);     // GSTG stages of [A|B]
    float*  Cs = reinterpret_cast<float*>(Sm + GSTG * STGH);

    const __half* Ab = (A != nullptr) ? A : g_attnh;

    int tid  = threadIdx.x;
    int lane = tid & 31;
    int warp = tid >> 5;
    int wm = warp >> 1;              // 0..3 -> 32-row group
    int wn = warp & 1;               // 0..1 -> 32-col group
    int m0 = blockIdx.y * 128;
    int n0 = blockIdx.x * 64;

    wmma::fragment<wmma::accumulator, 16, 16, 16, float> acc[2][2];
#pragma unroll
    for (int im = 0; im < 2; im++) {
#pragma unroll
        for (int jn = 0; jn < 2; jn++) {
            wmma::fill_fragment(acc[im][jn], 0.0f);
        }
    }

    // Loader: A tile 512 x16B chunks -> 2/thread (c=tid, tid+256);
    //         B tile 256 chunks -> 1/thread. chunk c: row c>>2, seg (c&3)*8.
    int ar0 = tid >> 2, as0 = (tid & 3) * 8;
    int ar1 = (tid + 256) >> 2, as1 = ((tid + 256) & 3) * 8;
    const __half* ApA0 = Ab + (size_t)(m0 + ar0) * K + as0;
    const __half* ApA1 = Ab + (size_t)(m0 + ar1) * K + as1;
    const __half* BpB  = Wt + (size_t)(n0 + ar0) * K + as0;
    int soA0 = ar0 * PADH + as0;
    int soA1 = ar1 * PADH + as1;
    int soB  = ATILEH + ar0 * PADH + as0;

    int NT = K / 32;

#pragma unroll
    for (int s = 0; s < GSTG - 1; s++) {
        if (s < NT) {
            __half* Sd = Sm + s * STGH;
            int k0 = s * 32;
            __pipeline_memcpy_async(Sd + soA0, ApA0 + k0, 16);
            __pipeline_memcpy_async(Sd + soA1, ApA1 + k0, 16);
            __pipeline_memcpy_async(Sd + soB,  BpB  + k0, 16);
        }
        __pipeline_commit();
    }

    for (int it = 0; it < NT; it++) {
        __pipeline_wait_prior(GSTG - 2);
        __syncthreads();

        int nx = it + GSTG - 1;
        if (nx < NT) {
            __half* Sd = Sm + (nx % GSTG) * STGH;
            int k0 = nx * 32;
            __pipeline_memcpy_async(Sd + soA0, ApA0 + k0, 16);
            __pipeline_memcpy_async(Sd + soA1, ApA1 + k0, 16);
            __pipeline_memcpy_async(Sd + soB,  BpB  + k0, 16);
        }
        __pipeline_commit();

        __half* Ac = Sm + (it % GSTG) * STGH;
        __half* Bc = Ac + ATILEH;
#pragma unroll
        for (int ks = 0; ks < 2; ks++) {
            int kk = ks * 16;
            wmma::fragment<wmma::matrix_b, 16, 16, 16, half, wmma::col_major> bf[2];
#pragma unroll
            for (int jn = 0; jn < 2; jn++) {
                wmma::load_matrix_sync(bf[jn], Bc + (wn * 32 + jn * 16) * PADH + kk, PADH);
            }
#pragma unroll
            for (int im = 0; im < 2; im++) {
                wmma::fragment<wmma::matrix_a, 16, 16, 16, half, wmma::row_major> af;
                wmma::load_matrix_sync(af, Ac + (wm * 32 + im * 16) * PADH + kk, PADH);
                wmma::mma_sync(acc[im][0], af, bf[0], acc[im][0]);
                wmma::mma_sync(acc[im][1], af, bf[1], acc[im][1]);
            }
        }
    }

    // Epilogue: per-warp 16x16 staging, then bias + write/scatter.
    float* cw = Cs + warp * 16 * CPAD;
    int er = lane >> 1;
    int ec = (lane & 1) * 8;
#pragma unroll
    for (int im = 0; im < 2; im++) {
#pragma unroll
        for (int jn = 0; jn < 2; jn++) {
            wmma::store_matrix_sync(cw, acc[im][jn], CPAD, wmma::mem_row_major);
            __syncwarp();
            int m = m0 + wm * 32 + im * 16 + er;
            int n = n0 + wn * 32 + jn * 16 + ec;
            float v[8];
#pragma unroll
            for (int t = 0; t < 8; t++) {
                v[t] = cw[er * CPAD + ec + t] + bias[n + t];
            }
            if (mode == 0) {
                float4 w0 = make_float4(v[0], v[1], v[2], v[3]);
                float4 w1 = make_float4(v[4], v[5], v[6], v[7]);
                *reinterpret_cast<float4*>(Cf + (size_t)m * N + n) = w0;
                *reinterpret_cast<float4*>(Cf + (size_t)m * N + n + 4) = w1;
            } else {
                int bb = m >> 11;
                int s  = m & (S_ - 1);
                int part = n >> 10;
                int nn = n & 1023;
                int hd = nn >> 6;
                int dd = nn & 63;
                __half* dst = g_vh;
                if (part == 0) dst = g_qh;
                if (part == 1) dst = g_kh;
                size_t off = (((size_t)(bb * H_ + hd)) * S_ + s) * DH_ + dd;
#pragma unroll
                for (int t = 0; t < 4; t++) {
                    __half2 hv = __floats2half2_rn(v[2 * t], v[2 * t + 1]);
                    *reinterpret_cast<__half2*>(dst + off + 2 * t) = hv;
                }
            }
            __syncwarp();
        }
    }
}

// ---------------------------------------------------------------------------
// WMMA fp16 attention (R12, unchanged): register-resident P, 128-key tiles,
// log2-domain S + h2exp2, ones-column row sums, 2-stage cp.async.
// ---------------------------------------------------------------------------
#define QPAD 72
#define KPADA 72
#define VPADA 88
#define TK 128
#define KTILE (TK * KPADA)
#define VTILE (TK * VPADA)
#define OPAD 84
#define SM_HALVES (128 * QPAD + 2 * KTILE + 2 * VTILE)
#define ATTN_SMEM (SM_HALVES * 2)

typedef wmma::fragment<wmma::matrix_a, 16, 16, 16, half, wmma::row_major> AFragH;

__global__ __launch_bounds__(256, 2) void attn_h()
{
    extern __shared__ char smraw[];
    __half* Qs = reinterpret_cast<__half*>(smraw);
    __half* Ks = Qs + 128 * QPAD;
    __half* Vs = Ks + 2 * KTILE;
    float*  Os = reinterpret_cast<float*>(smraw);

    int tid  = threadIdx.x;
    int lane = tid & 31;
    int warp = tid >> 5;
    int bh = blockIdx.y;
    int q0 = blockIdx.x * 128;

    const __half* Qg = g_qh + (size_t)bh * S_ * DH_;
    const __half* Kg = g_kh + (size_t)bh * S_ * DH_;
    const __half* Vg = g_vh + (size_t)bh * S_ * DH_;

    int krow = tid >> 2;
    int kc8 = (tid & 3) * 8;
    int koff = krow * KPADA + kc8;
    int voff = krow * VPADA + kc8;
    const __half* Kp = Kg + (size_t)krow * DH_ + kc8;
    const __half* Vp = Vg + (size_t)krow * DH_ + kc8;

    __pipeline_memcpy_async(Ks + koff, Kp, 16);
    __pipeline_memcpy_async(Ks + koff + 32, Kp + 32, 16);
    __pipeline_memcpy_async(Ks + 64 * KPADA + koff, Kp + 64 * DH_, 16);
    __pipeline_memcpy_async(Ks + 64 * KPADA + koff + 32, Kp + 64 * DH_ + 32, 16);
    __pipeline_memcpy_async(Vs + voff, Vp, 16);
    __pipeline_memcpy_async(Vs + voff + 32, Vp + 32, 16);
    __pipeline_memcpy_async(Vs + 64 * VPADA + voff, Vp + 64 * DH_, 16);
    __pipeline_memcpy_async(Vs + 64 * VPADA + voff + 32, Vp + 64 * DH_ + 32, 16);
    __pipeline_commit();

    {
        int r = tid & 127;
        int st = tid >> 7;
        __half* row = Vs + st * VTILE + r * VPADA;
        row[64] = __float2half(1.0f);
#pragma unroll
        for (int c = 65; c < 80; c++) {
            row[c] = __float2half(0.0f);
        }
    }

    // Stage Q, pre-scaled by 0.125 * log2(e)  (S accumulates in log2 domain)
    __half2 hscale = __floats2half2_rn(0.18033688011112042f, 0.18033688011112042f);
#pragma unroll
    for (int it = 0; it < 4; it++) {
        int sg = tid + it * 256;
        int r = sg >> 3;
        int c8 = (sg & 7) * 8;
        uint4 v = *reinterpret_cast<const uint4*>(Qg + (size_t)(q0 + r) * DH_ + c8);
        __half2* hp = reinterpret_cast<__half2*>(&v);
        hp[0] = __hmul2(hp[0], hscale);
        hp[1] = __hmul2(hp[1], hscale);
        hp[2] = __hmul2(hp[2], hscale);
        hp[3] = __hmul2(hp[3], hscale);
        *reinterpret_cast<uint4*>(Qs + r * QPAD + c8) = v;
    }
    __syncthreads();

    wmma::fragment<wmma::accumulator, 16, 16, 16, float> oacc[5];
#pragma unroll
    for (int dg = 0; dg < 5; dg++) {
        wmma::fill_fragment(oacc[dg], 0.0f);
    }

    const __half* Qw = Qs + (warp * 16) * QPAD;

    int NT = S_ / TK;
    for (int it = 0; it < NT; it++) {
        __pipeline_wait_prior(0);
        __syncthreads();

        if (it + 1 < NT) {
            int st = (it + 1) & 1;
            size_t go = (size_t)(it + 1) * TK * DH_;
            __half* Kd = Ks + st * KTILE;
            __half* Vd = Vs + st * VTILE;
            __pipeline_memcpy_async(Kd + koff, Kp + go, 16);
            __pipeline_memcpy_async(Kd + koff + 32, Kp + go + 32, 16);
            __pipeline_memcpy_async(Kd + 64 * KPADA + koff, Kp + go + 64 * DH_, 16);
            __pipeline_memcpy_async(Kd + 64 * KPADA + koff + 32, Kp + go + 64 * DH_ + 32, 16);
            __pipeline_memcpy_async(Vd + voff, Vp + go, 16);
            __pipeline_memcpy_async(Vd + voff + 32, Vp + go + 32, 16);
            __pipeline_memcpy_async(Vd + 64 * VPADA + voff, Vp + go + 64 * DH_, 16);
            __pipeline_memcpy_async(Vd + 64 * VPADA + voff + 32, Vp + go + 64 * DH_ + 32, 16);
        }
        __pipeline_commit();

        __half* Kc = Ks + (it & 1) * KTILE;
        __half* Vc = Vs + (it & 1) * VTILE;

        wmma::fragment<wmma::accumulator, 16, 16, 16, half> sacc[8];
#pragma unroll
        for (int ng = 0; ng < 8; ng++) {
            wmma::fill_fragment(sacc[ng], __float2half(0.0f));
        }
#pragma unroll
        for (int g = 0; g < 4; g++) {
            AFragH qf;
            wmma::load_matrix_sync(qf, Qw + g * 16, QPAD);
#pragma unroll
            for (int ng = 0; ng < 8; ng++) {
                wmma::fragment<wmma::matrix_b, 16, 16, 16, half, wmma::col_major> kf;
                wmma::load_matrix_sync(kf, Kc + (ng * 16) * KPADA + g * 16, KPADA);
                wmma::mma_sync(sacc[ng], qf, kf, sacc[ng]);
            }
        }

#pragma unroll
        for (int ng = 0; ng < 8; ng++) {
            __half2* sp = reinterpret_cast<__half2*>(&sacc[ng].x[0]);
#pragma unroll
            for (int e = 0; e < 4; e++) {
                sp[e] = h2exp2(sp[e]);
            }
        }

#pragma unroll
        for (int g = 0; g < 8; g++) {
            const AFragH& pf = reinterpret_cast<const AFragH&>(sacc[g]);
#pragma unroll
            for (int dg = 0; dg < 5; dg++) {
                wmma::fragment<wmma::matrix_b, 16, 16, 16, half, wmma::row_major> vf;
                wmma::load_matrix_sync(vf, Vc + (g * 16) * VPADA + dg * 16, VPADA);
                wmma::mma_sync(oacc[dg], pf, vf, oacc[dg]);
            }
        }
    }

    __syncthreads();
    float* Ow = Os + warp * 16 * OPAD;
#pragma unroll
    for (int dg = 0; dg < 5; dg++) {
        wmma::store_matrix_sync(Ow + dg * 16, oacc[dg], OPAD, wmma::mem_row_major);
    }
    __syncwarp();

    int er = lane >> 1;
    int ec = (lane & 1) * 32;
    float inv = 1.f / Ow[er * OPAD + 64];
    int bb = bh >> 4;
    int hd = bh & 15;
    int orow = q0 + warp * 16 + er;
    size_t base = ((size_t)(bb * S_ + orow)) * D_ + hd * 64 + ec;
#pragma unroll
    for (int t = 0; t < 16; t++) {
        float u0 = Ow[er * OPAD + ec + 2 * t] * inv;
        float u1 = Ow[er * OPAD + ec + 2 * t + 1] * inv;
        __half2 hv = __floats2half2_rn(u0, u1);
        *reinterpret_cast<__half2*>(g_attnh + base + 2 * t) = hv;
    }
}

// ---------------------------------------------------------------------------
extern "C" void kernel_launch(void* const* d_in, const int* in_sizes, int n_in,
                              void* d_out, int out_size)
{
    const float* x     = (const float*)d_in[0];
    const float* W_in  = (const float*)d_in[1];
    const float* b_in  = (const float*)d_in[2];
    const float* W_out = (const float*)d_in[3];
    const float* b_out = (const float*)d_in[4];
    float* out = (float*)d_out;

    __half2* xh = 0;
    __half2* wih = 0;
    __half2* woh = 0;
    cudaGetSymbolAddress((void**)&xh, g_xh);
    cudaGetSymbolAddress((void**)&wih, g_wih);
    cudaGetSymbolAddress((void**)&woh, g_woh);

    f2h3<<<(NA2 + NB2 + NC2 + 255) / 256, 256>>>(x, W_in, W_out, xh, wih, woh);

    cudaFuncSetAttribute(hgemm, cudaFuncAttributeMaxDynamicSharedMemorySize, HG_SMEM);
    cudaFuncSetAttribute(attn_h, cudaFuncAttributeMaxDynamicSharedMemorySize, ATTN_SMEM);

    hgemm<<<dim3(N3_ / 64, M_ / 128), 256, HG_SMEM>>>(
        (const __half*)xh, (const __half*)wih, b_in, nullptr, N3_, D_, 1);

    attn_h<<<dim3(S_ / 128, B_ * H_), 256, ATTN_SMEM>>>();

    hgemm<<<dim3(D_ / 64, M_ / 128), 256, HG_SMEM>>>(
        nullptr, (const __half*)woh, b_out, out, D_, D_, 0);
}

// round 16
// speedup vs baseline: 1.0455x; 1.0455x over previous
#include <cuda_runtime.h>
#include <cuda_fp16.h>
#include <cuda_pipeline.h>
#include <mma.h>

using namespace nvcuda;

#define B_   2
#define S_   2048
#define H_   16
#define DH_  64
#define D_   1024
#define M_   (B_ * S_)
#define N3_  (3 * D_)

// fp16 scratch (device globals; no allocs allowed)
__device__ __half g_xh[M_ * D_];
__device__ __half g_wih[N3_ * D_];
__device__ __half g_woh[D_ * D_];
__device__ __half g_qh[M_ * D_];
__device__ __half g_kh[M_ * D_];
__device__ __half g_vh[M_ * D_];
__device__ __half g_attnh[M_ * D_];

// ---------------- fused fp32 -> fp16 (float4 vectorized) ----------------
#define NA4 (M_ * D_ / 4)
#define NB4 (N3_ * D_ / 4)
#define NC4 (D_ * D_ / 4)

__global__ void f2h3(const float* __restrict__ a, const float* __restrict__ b,
                     const float* __restrict__ c,
                     __half* __restrict__ da, __half* __restrict__ db,
                     __half* __restrict__ dc) {
    int i = blockIdx.x * blockDim.x + threadIdx.x;
    const float* src;
    __half* dst;
    int j;
    if (i < NA4) {
        src = a; dst = da; j = i;
    } else if (i < NA4 + NB4) {
        src = b; dst = db; j = i - NA4;
    } else if (i < NA4 + NB4 + NC4) {
        src = c; dst = dc; j = i - NA4 - NB4;
    } else {
        return;
    }
    float4 v = reinterpret_cast<const float4*>(src)[j];
    __half2 h0 = __floats2half2_rn(v.x, v.y);
    __half2 h1 = __floats2half2_rn(v.z, v.w);
    uint32_t u0 = *reinterpret_cast<uint32_t*>(&h0);
    uint32_t u1 = *reinterpret_cast<uint32_t*>(&h1);
    reinterpret_cast<uint2*>(dst)[j] = make_uint2(u0, u1);
}

// ---------------------------------------------------------------------------
// WMMA fp16 GEMM with 3-stage cp.async pipeline: C = A @ Wt^T + bias.
// Block 128x128, BK=32, 8 warps (2x4), 256 threads. (measured best: R5-R12)
// mode 0: fp32 out to Cf. mode 1: scatter half to g_qh/g_kh/g_vh.
// A == nullptr means read g_attnh.
// ---------------------------------------------------------------------------
#define PADH 40
#define CPAD 20
#define GSTG 3
#define TILEH (128 * PADH)
#define HG_SMEM ((2 * GSTG * TILEH) * 2 + 8 * 16 * CPAD * 4)

__global__ __launch_bounds__(256) void hgemm(
    const __half* __restrict__ A, const __half* __restrict__ Wt,
    const float* __restrict__ bias, float* __restrict__ Cf,
    int N, int K, int mode)
{
    extern __shared__ char hsm[];
    __half* As = reinterpret_cast<__half*>(hsm);
    __half* Bs = As + GSTG * TILEH;
    float*  Cs = reinterpret_cast<float*>(Bs + GSTG * TILEH);

    const __half* Ab = (A != nullptr) ? A : g_attnh;

    int tid  = threadIdx.x;
    int lane = tid & 31;
    int warp = tid >> 5;
    int wm = warp >> 2;
    int wn = warp & 3;
    int m0 = blockIdx.y * 128;
    int n0 = blockIdx.x * 128;

    wmma::fragment<wmma::accumulator, 16, 16, 16, float> acc[4][2];
#pragma unroll
    for (int im = 0; im < 4; im++) {
#pragma unroll
        for (int jn = 0; jn < 2; jn++) {
            wmma::fill_fragment(acc[im][jn], 0.0f);
        }
    }

    int lrow = tid >> 2;
    int lseg = (tid & 3) * 8;
    const __half* Ap = Ab + (size_t)(m0 + lrow) * K + lseg;
    const __half* Bp = Wt + (size_t)(n0 + lrow) * K + lseg;
    int soff = lrow * PADH + lseg;

    int NT = K / 32;

#pragma unroll
    for (int s = 0; s < GSTG - 1; s++) {
        if (s < NT) {
            __half* Ad = As + s * TILEH;
            __half* Bd = Bs + s * TILEH;
            int k0 = s * 32;
            __pipeline_memcpy_async(Ad + soff, Ap + k0, 16);
            __pipeline_memcpy_async(Ad + 64 * PADH + soff, Ap + (size_t)64 * K + k0, 16);
            __pipeline_memcpy_async(Bd + soff, Bp + k0, 16);
            __pipeline_memcpy_async(Bd + 64 * PADH + soff, Bp + (size_t)64 * K + k0, 16);
        }
        __pipeline_commit();
    }

    for (int it = 0; it < NT; it++) {
        __pipeline_wait_prior(GSTG - 2);
        __syncthreads();

        int nx = it + GSTG - 1;
        if (nx < NT) {
            int st = nx % GSTG;
            __half* Ad = As + st * TILEH;
            __half* Bd = Bs + st * TILEH;
            int k0 = nx * 32;
            __pipeline_memcpy_async(Ad + soff, Ap + k0, 16);
            __pipeline_memcpy_async(Ad + 64 * PADH + soff, Ap + (size_t)64 * K + k0, 16);
            __pipeline_memcpy_async(Bd + soff, Bp + k0, 16);
            __pipeline_memcpy_async(Bd + 64 * PADH + soff, Bp + (size_t)64 * K + k0, 16);
        }
        __pipeline_commit();

        __half* Ac = As + (it % GSTG) * TILEH;
        __half* Bc = Bs + (it % GSTG) * TILEH;
#pragma unroll
        for (int ks = 0; ks < 2; ks++) {
            int kk = ks * 16;
            wmma::fragment<wmma::matrix_b, 16, 16, 16, half, wmma::col_major> bf[2];
#pragma unroll
            for (int jn = 0; jn < 2; jn++) {
                wmma::load_matrix_sync(bf[jn], Bc + (wn * 32 + jn * 16) * PADH + kk, PADH);
            }
#pragma unroll
            for (int im = 0; im < 4; im++) {
                wmma::fragment<wmma::matrix_a, 16, 16, 16, half, wmma::row_major> af;
                wmma::load_matrix_sync(af, Ac + (wm * 64 + im * 16) * PADH + kk, PADH);
                wmma::mma_sync(acc[im][0], af, bf[0], acc[im][0]);
                wmma::mma_sync(acc[im][1], af, bf[1], acc[im][1]);
            }
        }
    }

    // Epilogue: per-warp 16x16 staging, then bias + write/scatter.
    float* cw = Cs + warp * 16 * CPAD;
    int er = lane >> 1;
    int ec = (lane & 1) * 8;
#pragma unroll
    for (int im = 0; im < 4; im++) {
#pragma unroll
        for (int jn = 0; jn < 2; jn++) {
            wmma::store_matrix_sync(cw, acc[im][jn], CPAD, wmma::mem_row_major);
            __syncwarp();
            int m = m0 + wm * 64 + im * 16 + er;
            int n = n0 + wn * 32 + jn * 16 + ec;
            float v[8];
#pragma unroll
            for (int t = 0; t < 8; t++) {
                v[t] = cw[er * CPAD + ec + t] + bias[n + t];
            }
            if (mode == 0) {
                float4 w0 = make_float4(v[0], v[1], v[2], v[3]);
                float4 w1 = make_float4(v[4], v[5], v[6], v[7]);
                *reinterpret_cast<float4*>(Cf + (size_t)m * N + n) = w0;
                *reinterpret_cast<float4*>(Cf + (size_t)m * N + n + 4) = w1;
            } else {
                int bb = m >> 11;
                int s  = m & (S_ - 1);
                int part = n >> 10;
                int nn = n & 1023;
                int hd = nn >> 6;
                int dd = nn & 63;
                __half* dst = g_vh;
                if (part == 0) dst = g_qh;
                if (part == 1) dst = g_kh;
                size_t off = (((size_t)(bb * H_ + hd)) * S_ + s) * DH_ + dd;
#pragma unroll
                for (int t = 0; t < 4; t++) {
                    __half2 hv = __floats2half2_rn(v[2 * t], v[2 * t + 1]);
                    *reinterpret_cast<__half2*>(dst + off + 2 * t) = hv;
                }
            }
            __syncwarp();
        }
    }
}

// ---------------------------------------------------------------------------
// WMMA fp16 attention (R12, measured best): register-resident P, 128-key
// tiles, log2-domain S + h2exp2, ones-column row sums, 2-stage cp.async.
// ---------------------------------------------------------------------------
#define QPAD 72
#define KPADA 72
#define VPADA 88
#define TK 128
#define KTILE (TK * KPADA)
#define VTILE (TK * VPADA)
#define OPAD 84
#define SM_HALVES (128 * QPAD + 2 * KTILE + 2 * VTILE)
#define ATTN_SMEM (SM_HALVES * 2)

typedef wmma::fragment<wmma::matrix_a, 16, 16, 16, half, wmma::row_major> AFragH;

__global__ __launch_bounds__(256, 2) void attn_h()
{
    extern __shared__ char smraw[];
    __half* Qs = reinterpret_cast<__half*>(smraw);
    __half* Ks = Qs + 128 * QPAD;
    __half* Vs = Ks + 2 * KTILE;
    float*  Os = reinterpret_cast<float*>(smraw);

    int tid  = threadIdx.x;
    int lane = tid & 31;
    int warp = tid >> 5;
    int bh = blockIdx.y;
    int q0 = blockIdx.x * 128;

    const __half* Qg = g_qh + (size_t)bh * S_ * DH_;
    const __half* Kg = g_kh + (size_t)bh * S_ * DH_;
    const __half* Vg = g_vh + (size_t)bh * S_ * DH_;

    int krow = tid >> 2;
    int kc8 = (tid & 3) * 8;
    int koff = krow * KPADA + kc8;
    int voff = krow * VPADA + kc8;
    const __half* Kp = Kg + (size_t)krow * DH_ + kc8;
    const __half* Vp = Vg + (size_t)krow * DH_ + kc8;

    __pipeline_memcpy_async(Ks + koff, Kp, 16);
    __pipeline_memcpy_async(Ks + koff + 32, Kp + 32, 16);
    __pipeline_memcpy_async(Ks + 64 * KPADA + koff, Kp + 64 * DH_, 16);
    __pipeline_memcpy_async(Ks + 64 * KPADA + koff + 32, Kp + 64 * DH_ + 32, 16);
    __pipeline_memcpy_async(Vs + voff, Vp, 16);
    __pipeline_memcpy_async(Vs + voff + 32, Vp + 32, 16);
    __pipeline_memcpy_async(Vs + 64 * VPADA + voff, Vp + 64 * DH_, 16);
    __pipeline_memcpy_async(Vs + 64 * VPADA + voff + 32, Vp + 64 * DH_ + 32, 16);
    __pipeline_commit();

    {
        int r = tid & 127;
        int st = tid >> 7;
        __half* row = Vs + st * VTILE + r * VPADA;
        row[64] = __float2half(1.0f);
#pragma unroll
        for (int c = 65; c < 80; c++) {
            row[c] = __float2half(0.0f);
        }
    }

    // Stage Q, pre-scaled by 0.125 * log2(e)  (S accumulates in log2 domain)
    __half2 hscale = __floats2half2_rn(0.18033688011112042f, 0.18033688011112042f);
#pragma unroll
    for (int it = 0; it < 4; it++) {
        int sg = tid + it * 256;
        int r = sg >> 3;
        int c8 = (sg & 7) * 8;
        uint4 v = *reinterpret_cast<const uint4*>(Qg + (size_t)(q0 + r) * DH_ + c8);
        __half2* hp = reinterpret_cast<__half2*>(&v);
        hp[0] = __hmul2(hp[0], hscale);
        hp[1] = __hmul2(hp[1], hscale);
        hp[2] = __hmul2(hp[2], hscale);
        hp[3] = __hmul2(hp[3], hscale);
        *reinterpret_cast<uint4*>(Qs + r * QPAD + c8) = v;
    }
    __syncthreads();

    wmma::fragment<wmma::accumulator, 16, 16, 16, float> oacc[5];
#pragma unroll
    for (int dg = 0; dg < 5; dg++) {
        wmma::fill_fragment(oacc[dg], 0.0f);
    }

    const __half* Qw = Qs + (warp * 16) * QPAD;

    int NT = S_ / TK;
    for (int it = 0; it < NT; it++) {
        __pipeline_wait_prior(0);
        __syncthreads();

        if (it + 1 < NT) {
            int st = (it + 1) & 1;
            size_t go = (size_t)(it + 1) * TK * DH_;
            __half* Kd = Ks + st * KTILE;
            __half* Vd = Vs + st * VTILE;
            __pipeline_memcpy_async(Kd + koff, Kp + go, 16);
            __pipeline_memcpy_async(Kd + koff + 32, Kp + go + 32, 16);
            __pipeline_memcpy_async(Kd + 64 * KPADA + koff, Kp + go + 64 * DH_, 16);
            __pipeline_memcpy_async(Kd + 64 * KPADA + koff + 32, Kp + go + 64 * DH_ + 32, 16);
            __pipeline_memcpy_async(Vd + voff, Vp + go, 16);
            __pipeline_memcpy_async(Vd + voff + 32, Vp + go + 32, 16);
            __pipeline_memcpy_async(Vd + 64 * VPADA + voff, Vp + go + 64 * DH_, 16);
            __pipeline_memcpy_async(Vd + 64 * VPADA + voff + 32, Vp + go + 64 * DH_ + 32, 16);
        }
        __pipeline_commit();

        __half* Kc = Ks + (it & 1) * KTILE;
        __half* Vc = Vs + (it & 1) * VTILE;

        wmma::fragment<wmma::accumulator, 16, 16, 16, half> sacc[8];
#pragma unroll
        for (int ng = 0; ng < 8; ng++) {
            wmma::fill_fragment(sacc[ng], __float2half(0.0f));
        }
#pragma unroll
        for (int g = 0; g < 4; g++) {
            AFragH qf;
            wmma::load_matrix_sync(qf, Qw + g * 16, QPAD);
#pragma unroll
            for (int ng = 0; ng < 8; ng++) {
                wmma::fragment<wmma::matrix_b, 16, 16, 16, half, wmma::col_major> kf;
                wmma::load_matrix_sync(kf, Kc + (ng * 16) * KPADA + g * 16, KPADA);
                wmma::mma_sync(sacc[ng], qf, kf, sacc[ng]);
            }
        }

#pragma unroll
        for (int ng = 0; ng < 8; ng++) {
            __half2* sp = reinterpret_cast<__half2*>(&sacc[ng].x[0]);
#pragma unroll
            for (int e = 0; e < 4; e++) {
                sp[e] = h2exp2(sp[e]);
            }
        }

#pragma unroll
        for (int g = 0; g < 8; g++) {
            const AFragH& pf = reinterpret_cast<const AFragH&>(sacc[g]);
#pragma unroll
            for (int dg = 0; dg < 5; dg++) {
                wmma::fragment<wmma::matrix_b, 16, 16, 16, half, wmma::row_major> vf;
                wmma::load_matrix_sync(vf, Vc + (g * 16) * VPADA + dg * 16, VPADA);
                wmma::mma_sync(oacc[dg], pf, vf, oacc[dg]);
            }
        }
    }

    __syncthreads();
    float* Ow = Os + warp * 16 * OPAD;
#pragma unroll
    for (int dg = 0; dg < 5; dg++) {
        wmma::store_matrix_sync(Ow + dg * 16, oacc[dg], OPAD, wmma::mem_row_major);
    }
    __syncwarp();

    int er = lane >> 1;
    int ec = (lane & 1) * 32;
    float inv = 1.f / Ow[er * OPAD + 64];
    int bb = bh >> 4;
    int hd = bh & 15;
    int orow = q0 + warp * 16 + er;
    size_t base = ((size_t)(bb * S_ + orow)) * D_ + hd * 64 + ec;
#pragma unroll
    for (int t = 0; t < 16; t++) {
        float u0 = Ow[er * OPAD + ec + 2 * t] * inv;
        float u1 = Ow[er * OPAD + ec + 2 * t + 1] * inv;
        __half2 hv = __floats2half2_rn(u0, u1);
        *reinterpret_cast<__half2*>(g_attnh + base + 2 * t) = hv;
    }
}

// ---------------------------------------------------------------------------
extern "C" void kernel_launch(void* const* d_in, const int* in_sizes, int n_in,
                              void* d_out, int out_size)
{
    const float* x     = (const float*)d_in[0];
    const float* W_in  = (const float*)d_in[1];
    const float* b_in  = (const float*)d_in[2];
    const float* W_out = (const float*)d_in[3];
    const float* b_out = (const float*)d_in[4];
    float* out = (float*)d_out;

    __half* xh = 0;
    __half* wih = 0;
    __half* woh = 0;
    cudaGetSymbolAddress((void**)&xh, g_xh);
    cudaGetSymbolAddress((void**)&wih, g_wih);
    cudaGetSymbolAddress((void**)&woh, g_woh);

    f2h3<<<(NA4 + NB4 + NC4 + 255) / 256, 256>>>(x, W_in, W_out, xh, wih, woh);

    cudaFuncSetAttribute(hgemm, cudaFuncAttributeMaxDynamicSharedMemorySize, HG_SMEM);
    cudaFuncSetAttribute(attn_h, cudaFuncAttributeMaxDynamicSharedMemorySize, ATTN_SMEM);

    hgemm<<<dim3(N3_ / 128, M_ / 128), 256, HG_SMEM>>>(
        (const __half*)xh, (const __half*)wih, b_in, nullptr, N3_, D_, 1);

    attn_h<<<dim3(S_ / 128, B_ * H_), 256, ATTN_SMEM>>>();

    hgemm<<<dim3(D_ / 128, M_ / 128), 256, HG_SMEM>>>(
        nullptr, (const __half*)woh, b_out, out, D_, D_, 0);
}